// round 1
// baseline (speedup 1.0000x reference)
#include <cuda_runtime.h>
#include <cuda_bf16.h>
#include <math.h>

// Problem constants
#define BATCH 64
#define TLEN  1024
#define NF    512
#define NH    512
#define NK    500
#define MROWS (BATCH * TLEN)   // 65536

// GEMM tiling
#define BM 128
#define BN 128
#define BK 8
#define TM 8
#define TN 8
#define NTILES (NH / BN)       // 4

// Scratch (device globals: no runtime allocation allowed)
__device__ float g_po[(size_t)MROWS * NTILES * 2];  // partial o per column tile: [M][4][2]
__device__ float g_o[(size_t)MROWS * 2];            // o = tanh(FM@W1+b1)@W2 + b2

// ---------------------------------------------------------------------------
// Kernel A: fused GEMM1 + tanh + partial projection onto W2
// h_tile = tanh(FM_tile @ W1_tile + b1);  po[m, nt, j] = sum_{n in tile} h * W2[n, j]
// ---------------------------------------------------------------------------
__global__ __launch_bounds__(256, 2)
void mlp_gemm_kernel(const float* __restrict__ FM,
                     const float* __restrict__ W1,
                     const float* __restrict__ b1,
                     const float* __restrict__ W2)
{
    __shared__ float smem[4096];          // 16KB: As(1024)+Bs(1024) main loop; red(4096) epilogue
    float* As = smem;                     // [BK][BM]
    float* Bs = smem + BM * BK;           // [BK][BN]

    const int mt  = blockIdx.x;           // 512 row tiles
    const int nt  = blockIdx.y;           // 4 col tiles
    const int tid = threadIdx.x;
    const int ty  = tid >> 4;             // 0..15
    const int tx  = tid & 15;             // 0..15

    const float* Ab = FM + (size_t)mt * BM * NF;
    const float* Bb = W1 + nt * BN;

    float acc[TM][TN];
#pragma unroll
    for (int i = 0; i < TM; i++)
#pragma unroll
        for (int j = 0; j < TN; j++) acc[i][j] = 0.f;

    const int arow = tid >> 1;            // 0..127
    const int acol = (tid & 1) * 4;       // 0 or 4
    const int brow = tid >> 5;            // 0..7
    const int bcol = (tid & 31) * 4;      // 0..124

    for (int kt = 0; kt < NF; kt += BK) {
        float4 av = *(const float4*)(Ab + (size_t)arow * NF + kt + acol);
        float4 bv = *(const float4*)(Bb + (size_t)(kt + brow) * NH + bcol);
        As[(acol + 0) * BM + arow] = av.x;
        As[(acol + 1) * BM + arow] = av.y;
        As[(acol + 2) * BM + arow] = av.z;
        As[(acol + 3) * BM + arow] = av.w;
        *(float4*)(Bs + brow * BN + bcol) = bv;
        __syncthreads();

#pragma unroll
        for (int k = 0; k < BK; k++) {
            float a[TM], b[TN];
            float4 t;
            t = *(const float4*)&As[k * BM + ty * TM];     a[0]=t.x; a[1]=t.y; a[2]=t.z; a[3]=t.w;
            t = *(const float4*)&As[k * BM + ty * TM + 4]; a[4]=t.x; a[5]=t.y; a[6]=t.z; a[7]=t.w;
            t = *(const float4*)&Bs[k * BN + tx * TN];     b[0]=t.x; b[1]=t.y; b[2]=t.z; b[3]=t.w;
            t = *(const float4*)&Bs[k * BN + tx * TN + 4]; b[4]=t.x; b[5]=t.y; b[6]=t.z; b[7]=t.w;
#pragma unroll
            for (int i = 0; i < TM; i++)
#pragma unroll
                for (int j = 0; j < TN; j++)
                    acc[i][j] = fmaf(a[i], b[j], acc[i][j]);
        }
        __syncthreads();
    }

    // Epilogue: tanh + partial projection, deterministic smem reduction over tx
    const int nbase = nt * BN + tx * TN;
    float w2a[TN], w2b[TN], bb[TN];
#pragma unroll
    for (int j = 0; j < TN; j++) {
        w2a[j] = W2[(nbase + j) * 2 + 0];
        w2b[j] = W2[(nbase + j) * 2 + 1];
        bb[j]  = b1[nbase + j];
    }

    float p0[TM], p1[TM];
#pragma unroll
    for (int i = 0; i < TM; i++) {
        float s0 = 0.f, s1 = 0.f;
#pragma unroll
        for (int j = 0; j < TN; j++) {
            float h = tanhf(acc[i][j] + bb[j]);
            s0 = fmaf(h, w2a[j], s0);
            s1 = fmaf(h, w2b[j], s1);
        }
        p0[i] = s0; p1[i] = s1;
    }

    __syncthreads();  // done with As/Bs, reuse as reduction buffer
    float* red = smem;                    // [row*2+jj][16(tx)]
#pragma unroll
    for (int i = 0; i < TM; i++) {
        int row = ty * TM + i;
        red[(row * 2 + 0) * 16 + tx] = p0[i];
        red[(row * 2 + 1) * 16 + tx] = p1[i];
    }
    __syncthreads();

    // 256 values (128 rows x 2), one per thread
    {
        float s = 0.f;
#pragma unroll
        for (int t2 = 0; t2 < 16; t2++) s += red[tid * 16 + t2];
        int row = tid >> 1;
        int jj  = tid & 1;
        g_po[(size_t)(mt * BM + row) * (NTILES * 2) + nt * 2 + jj] = s;
    }
}

// ---------------------------------------------------------------------------
// Kernel B: o[m,j] = b2[j] + sum_nt po[m,nt,j]
// ---------------------------------------------------------------------------
__global__ void reduce_o_kernel(const float* __restrict__ b2)
{
    int m = blockIdx.x * blockDim.x + threadIdx.x;
    if (m >= MROWS) return;
    const float* p = &g_po[(size_t)m * (NTILES * 2)];
    float o0 = b2[0], o1 = b2[1];
#pragma unroll
    for (int nt = 0; nt < NTILES; nt++) {
        o0 += p[nt * 2 + 0];
        o1 += p[nt * 2 + 1];
    }
    g_o[(size_t)m * 2 + 0] = o0;
    g_o[(size_t)m * 2 + 1] = o1;
}

// ---------------------------------------------------------------------------
// Kernel C: parallel HMM scan. One block per batch, one thread per chain.
// Each thread owns chain c and walks its visits in time order.
// ---------------------------------------------------------------------------
__device__ __forceinline__ float lse2(float a, float b)
{
    float m = fmaxf(a, b);
    float d = fabsf(a - b);
    return m + log1pf(expf(-d));
}

__global__ __launch_bounds__(512)
void scan_kernel(const int* __restrict__ corr,
                 const int* __restrict__ kc,
                 const float* __restrict__ trans_logits,
                 const float* __restrict__ obs_logits,
                 const float* __restrict__ init_logits,
                 float* __restrict__ out)
{
    __shared__ int kcs[TLEN];
    __shared__ int crs[TLEN];
    const int b = blockIdx.x;

    for (int t = threadIdx.x; t < TLEN; t += blockDim.x) {
        kcs[t] = kc[b * TLEN + t];
        crs[t] = corr[b * TLEN + t];
    }
    __syncthreads();

    const int c = threadIdx.x;
    if (c >= NK) return;

    // log_t[i][s] = trans_logits[c,i,s] - logsumexp_i(trans_logits[c,:,s])
    float t00 = trans_logits[c * 4 + 0];  // [i=0][s=0]
    float t01 = trans_logits[c * 4 + 1];  // [i=0][s=1]
    float t10 = trans_logits[c * 4 + 2];  // [i=1][s=0]
    float t11 = trans_logits[c * 4 + 3];  // [i=1][s=1]
    float ls0 = lse2(t00, t10);           // column s=0 over i
    float ls1 = lse2(t01, t11);           // column s=1 over i
    float lt00 = t00 - ls0, lt10 = t10 - ls0;
    float lt01 = t01 - ls1, lt11 = t11 - ls1;

    float i0 = init_logits[c * 2 + 0];
    float i1 = init_logits[c * 2 + 1];
    float li = lse2(i0, i1);
    float la0 = i0 - li, la1 = i1 - li;

    float ol00 = obs_logits[c * 4 + 0];   // [s=0][j=0]
    float ol01 = obs_logits[c * 4 + 1];   // [s=0][j=1]
    float ol10 = obs_logits[c * 4 + 2];   // [s=1][j=0]
    float ol11 = obs_logits[c * 4 + 3];   // [s=1][j=1]

    for (int t = 0; t < TLEN; t++) {
        if (kcs[t] == c) {
            const int y = crs[t];
            const size_t idx = (size_t)(b * TLEN + t) * 2;
            float o0 = g_o[idx + 0];
            float o1 = g_o[idx + 1];

            // log_obs[s][j] = log_softmax_j(obs_logits[c,s,j] + fv[s,j]),
            // fv[s,0] = o_s, fv[s,1] = -o_s
            float e00 = ol00 + o0, e01 = ol01 - o0;
            float l0  = lse2(e00, e01);
            float lo00 = e00 - l0, lo01 = e01 - l0;
            float e10 = ol10 + o1, e11 = ol11 - o1;
            float l1  = lse2(e10, e11);
            float lo10 = e10 - l1, lo11 = e11 - l1;

            // output: normalized log_py over j
            float py0 = lse2(lo00 + la0, lo10 + la1);
            float py1 = lse2(lo01 + la0, lo11 + la1);
            float pn  = lse2(py0, py1);
            out[idx + 0] = py0 - pn;
            out[idx + 1] = py1 - pn;

            // update: new_la[i] = lse_s(lp[s] + la[s] + log_t[i][s])
            float lp0 = y ? lo01 : lo00;
            float lp1 = y ? lo11 : lo10;
            float na0 = lse2(lp0 + la0 + lt00, lp1 + la1 + lt01);
            float na1 = lse2(lp0 + la0 + lt10, lp1 + la1 + lt11);
            la0 = na0; la1 = na1;
        }
    }
}

// ---------------------------------------------------------------------------
// Launch
// Inputs (metadata order): corr, kc, FM, W1, b1, W2, b2, trans_logits,
//                          obs_logits, init_logits. Output: float32 [B,T,2].
// ---------------------------------------------------------------------------
extern "C" void kernel_launch(void* const* d_in, const int* in_sizes, int n_in,
                              void* d_out, int out_size)
{
    const int*   corr = (const int*)  d_in[0];
    const int*   kc   = (const int*)  d_in[1];
    const float* FM   = (const float*)d_in[2];
    const float* W1   = (const float*)d_in[3];
    const float* b1   = (const float*)d_in[4];
    const float* W2   = (const float*)d_in[5];
    const float* b2   = (const float*)d_in[6];
    const float* trl  = (const float*)d_in[7];
    const float* obl  = (const float*)d_in[8];
    const float* inl  = (const float*)d_in[9];
    float* out = (float*)d_out;

    dim3 gridA(MROWS / BM, NTILES);
    mlp_gemm_kernel<<<gridA, 256>>>(FM, W1, b1, W2);

    reduce_o_kernel<<<(MROWS + 255) / 256, 256>>>(b2);

    scan_kernel<<<BATCH, 512>>>(corr, kc, trl, obl, inl, out);
}

// round 5
// speedup vs baseline: 1.9512x; 1.9512x over previous
#include <cuda_runtime.h>
#include <cuda_bf16.h>
#include <math.h>
#include <stdint.h>

// ---------------------------------------------------------------------------
// Problem constants
// ---------------------------------------------------------------------------
#define BATCH 64
#define TLEN  1024
#define NF    512
#define NH    512
#define NK    500
#define MROWS (BATCH * TLEN)   // 65536

// GEMM config (warp-level HMMA, split-bf16 3-pass => K_eff = 3*512 = 1536)
#define BM 128
#define BN 128
#define BK 32                  // bf16 elems per k-chunk
#define KCHUNKS 48             // 1536 / 32
#define STAGES 3

#define A_PITCH 40                     // bf16 elems per smem A row (32 + 8 pad)
#define A_ST_BYTES (BM * A_PITCH * 2)  // 10240
#define B_ST_BYTES (BK * BN * 2)       // 8192
#define ST_BYTES (A_ST_BYTES + B_ST_BYTES)  // 18432
#define DYN_SMEM (STAGES * ST_BYTES)        // 55296

// ---------------------------------------------------------------------------
// Device scratch (static device globals; runtime allocation is forbidden)
// ---------------------------------------------------------------------------
__device__ __align__(16) __nv_bfloat16 g_Ah[(size_t)MROWS * NF];  // 64 MB
__device__ __align__(16) __nv_bfloat16 g_Al[(size_t)MROWS * NF];  // 64 MB
__device__ __align__(16) __nv_bfloat16 g_Bh[(size_t)NF * NH];     // 512 KB
__device__ __align__(16) __nv_bfloat16 g_Bl[(size_t)NF * NH];     // 512 KB
__device__ float g_po[(size_t)MROWS * 4 * 2];                     // 2 MB
__device__ float g_o[(size_t)MROWS * 2];                          // 512 KB

// ---------------------------------------------------------------------------
// PTX helpers (all baseline sm_80-era: valid for compute_103 target)
// ---------------------------------------------------------------------------
__device__ __forceinline__ uint32_t smem_u32(const void* p) {
    uint32_t a;
    asm("{ .reg .u64 t; cvta.to.shared.u64 t, %1; cvt.u32.u64 %0, t; }" : "=r"(a) : "l"(p));
    return a;
}
__device__ __forceinline__ void cpa16(uint32_t dst, const void* src) {
    asm volatile("cp.async.cg.shared.global [%0], [%1], 16;" :: "r"(dst), "l"(src));
}
__device__ __forceinline__ void cp_commit() {
    asm volatile("cp.async.commit_group;" ::: "memory");
}
__device__ __forceinline__ void cp_wait1() {
    asm volatile("cp.async.wait_group 1;" ::: "memory");
}
__device__ __forceinline__ void ldm_x4(uint32_t r[4], uint32_t addr) {
    asm volatile("ldmatrix.sync.aligned.m8n8.x4.shared.b16 {%0,%1,%2,%3}, [%4];"
                 : "=r"(r[0]), "=r"(r[1]), "=r"(r[2]), "=r"(r[3]) : "r"(addr));
}
__device__ __forceinline__ void ldm_x4_t(uint32_t& r0, uint32_t& r1, uint32_t& r2,
                                         uint32_t& r3, uint32_t addr) {
    asm volatile("ldmatrix.sync.aligned.m8n8.x4.trans.shared.b16 {%0,%1,%2,%3}, [%4];"
                 : "=r"(r0), "=r"(r1), "=r"(r2), "=r"(r3) : "r"(addr));
}
__device__ __forceinline__ void mma_bf16(float c[4], const uint32_t a[4], const uint32_t b[2]) {
    asm volatile(
        "mma.sync.aligned.m16n8k16.row.col.f32.bf16.bf16.f32 "
        "{%0,%1,%2,%3}, {%4,%5,%6,%7}, {%8,%9}, {%0,%1,%2,%3};"
        : "+f"(c[0]), "+f"(c[1]), "+f"(c[2]), "+f"(c[3])
        : "r"(a[0]), "r"(a[1]), "r"(a[2]), "r"(a[3]), "r"(b[0]), "r"(b[1]));
}

// ---------------------------------------------------------------------------
// Prep: split fp32 -> bf16 hi/lo pairs
// ---------------------------------------------------------------------------
__global__ void prep_a_kernel(const float* __restrict__ FM)
{
    size_t i = ((size_t)blockIdx.x * 256 + threadIdx.x) * 4;
    float4 v = *(const float4*)(FM + i);
    __nv_bfloat16 h0 = __float2bfloat16_rn(v.x);
    __nv_bfloat16 h1 = __float2bfloat16_rn(v.y);
    __nv_bfloat16 h2 = __float2bfloat16_rn(v.z);
    __nv_bfloat16 h3 = __float2bfloat16_rn(v.w);
    __nv_bfloat16 l0 = __float2bfloat16_rn(v.x - __bfloat162float(h0));
    __nv_bfloat16 l1 = __float2bfloat16_rn(v.y - __bfloat162float(h1));
    __nv_bfloat16 l2 = __float2bfloat16_rn(v.z - __bfloat162float(h2));
    __nv_bfloat16 l3 = __float2bfloat16_rn(v.w - __bfloat162float(h3));
    *(__nv_bfloat162*)(g_Ah + i)     = __nv_bfloat162{h0, h1};
    *(__nv_bfloat162*)(g_Ah + i + 2) = __nv_bfloat162{h2, h3};
    *(__nv_bfloat162*)(g_Al + i)     = __nv_bfloat162{l0, l1};
    *(__nv_bfloat162*)(g_Al + i + 2) = __nv_bfloat162{l2, l3};
}

__global__ void prep_b_kernel(const float* __restrict__ W1)
{
    size_t i = ((size_t)blockIdx.x * 256 + threadIdx.x) * 4;
    float4 v = *(const float4*)(W1 + i);
    __nv_bfloat16 h0 = __float2bfloat16_rn(v.x);
    __nv_bfloat16 h1 = __float2bfloat16_rn(v.y);
    __nv_bfloat16 h2 = __float2bfloat16_rn(v.z);
    __nv_bfloat16 h3 = __float2bfloat16_rn(v.w);
    __nv_bfloat16 l0 = __float2bfloat16_rn(v.x - __bfloat162float(h0));
    __nv_bfloat16 l1 = __float2bfloat16_rn(v.y - __bfloat162float(h1));
    __nv_bfloat16 l2 = __float2bfloat16_rn(v.z - __bfloat162float(h2));
    __nv_bfloat16 l3 = __float2bfloat16_rn(v.w - __bfloat162float(h3));
    *(__nv_bfloat162*)(g_Bh + i)     = __nv_bfloat162{h0, h1};
    *(__nv_bfloat162*)(g_Bh + i + 2) = __nv_bfloat162{h2, h3};
    *(__nv_bfloat162*)(g_Bl + i)     = __nv_bfloat162{l0, l1};
    *(__nv_bfloat162*)(g_Bl + i + 2) = __nv_bfloat162{l2, l3};
}

// ---------------------------------------------------------------------------
// GEMM: warp-level bf16 HMMA, 3-stage cp.async pipeline, fused tanh+W2 epilogue
// grid = (4 n-tiles, 512 m-tiles), 256 threads (8 warps: warp_m 0-1, warp_n 0-3)
// K loop: 48 chunks of 32; seg0 = Ah*Bh, seg1 = Ah*Bl, seg2 = Al*Bh.
// ---------------------------------------------------------------------------
extern __shared__ unsigned char dynsmem[];

__device__ __forceinline__ void load_stage(int st, int kc, int mt, int nt,
                                           uint32_t smbase, int tid)
{
    const int seg = kc >> 4;
    const int k0  = (kc & 15) * BK;
    const __nv_bfloat16* As = (seg < 2 ? g_Ah : g_Al) + (size_t)mt * BM * NF + k0;
    const __nv_bfloat16* Bs = (seg == 1 ? g_Bl : g_Bh) + (size_t)k0 * NH + nt * BN;
    const uint32_t sa = smbase + st * ST_BYTES;
    const uint32_t sb = sa + A_ST_BYTES;
#pragma unroll
    for (int h = 0; h < 2; ++h) {
        int id = tid + h * 256;              // 512 chunks of 16B
        int m  = id >> 2;
        int ca = id & 3;
        cpa16(sa + (uint32_t)m * (A_PITCH * 2) + ca * 16,
              As + (size_t)m * NF + ca * 8);
    }
#pragma unroll
    for (int h = 0; h < 2; ++h) {
        int id = tid + h * 256;              // 512 chunks of 16B
        int k  = id >> 4;
        int cb = id & 15;
        cpa16(sb + ((uint32_t)k * 16 + (cb ^ (k & 7))) * 16,
              Bs + (size_t)k * NH + cb * 8);
    }
}

__global__ __launch_bounds__(256)
void gemm_hmma(const float* __restrict__ b1, const float* __restrict__ W2)
{
    const int tid    = threadIdx.x;
    const int lane   = tid & 31;
    const int wid    = tid >> 5;
    const int warp_m = wid & 1;          // 0..1 -> 64-row halves
    const int warp_n = wid >> 1;         // 0..3 -> 32-col strips
    const int nt     = blockIdx.x;       // 0..3
    const int mt     = blockIdx.y;       // 0..511
    const uint32_t smbase = smem_u32(dynsmem);

    float c[4][4][4];
#pragma unroll
    for (int i = 0; i < 4; ++i)
#pragma unroll
        for (int j = 0; j < 4; ++j)
#pragma unroll
            for (int r = 0; r < 4; ++r) c[i][j][r] = 0.f;

#pragma unroll
    for (int s = 0; s < STAGES - 1; ++s) {
        load_stage(s, s, mt, nt, smbase, tid);
        cp_commit();
    }

    for (int kc = 0; kc < KCHUNKS; ++kc) {
        cp_wait1();
        __syncthreads();

        // prefetch next stage
        const int next = kc + STAGES - 1;
        if (next < KCHUNKS) load_stage(next % STAGES, next, mt, nt, smbase, tid);
        cp_commit();

        const int st = kc % STAGES;
        const uint32_t sa = smbase + st * ST_BYTES;
        const uint32_t sb = sa + A_ST_BYTES;

#pragma unroll
        for (int ks = 0; ks < 2; ++ks) {       // two k16 steps per chunk
            const int k0 = ks * 16;
            uint32_t a[4][4];
#pragma unroll
            for (int i = 0; i < 4; ++i) {
                int m    = warp_m * 64 + i * 16 + (lane & 15);
                int koff = k0 + ((lane >> 4) << 3);
                ldm_x4(a[i], sa + (uint32_t)m * (A_PITCH * 2) + (uint32_t)koff * 2);
            }
            uint32_t b[4][2];
#pragma unroll
            for (int j2 = 0; j2 < 2; ++j2) {   // each x4.trans = two n8 frags
                int k    = k0 + (lane & 15);
                int clog = ((warp_n * 32 + j2 * 16) >> 3) + (lane >> 4);
                uint32_t addr = sb + ((uint32_t)k * 16 + (uint32_t)(clog ^ (k & 7))) * 16;
                uint32_t r0, r1, r2, r3;
                ldm_x4_t(r0, r1, r2, r3, addr);
                b[j2 * 2][0]     = r0; b[j2 * 2][1]     = r1;
                b[j2 * 2 + 1][0] = r2; b[j2 * 2 + 1][1] = r3;
            }
#pragma unroll
            for (int i = 0; i < 4; ++i)
#pragma unroll
                for (int j = 0; j < 4; ++j)
                    mma_bf16(c[i][j], a[i], b[j]);
        }
    }

    // ---- fused epilogue: tanh + W2 projection, partial sums over this n-tile
    __syncthreads();
    float* red = (float*)dynsmem;            // [128 rows][2 outs][16 slots] = 16KB

    // per-thread column constants (8 columns: 4 n-frags x 2)
    float b1v[4][2], w2a[4][2], w2b[4][2];
#pragma unroll
    for (int j = 0; j < 4; ++j)
#pragma unroll
        for (int cc = 0; cc < 2; ++cc) {
            int gn = nt * BN + warp_n * 32 + j * 8 + (lane & 3) * 2 + cc;
            b1v[j][cc] = b1[gn];
            w2a[j][cc] = W2[gn * 2 + 0];
            w2b[j][cc] = W2[gn * 2 + 1];
        }

#pragma unroll
    for (int i = 0; i < 4; ++i) {
#pragma unroll
        for (int rh = 0; rh < 2; ++rh) {
            float p0 = 0.f, p1 = 0.f;
#pragma unroll
            for (int j = 0; j < 4; ++j)
#pragma unroll
                for (int cc = 0; cc < 2; ++cc) {
                    float h = tanhf(c[i][j][rh * 2 + cc] + b1v[j][cc]);
                    p0 = fmaf(h, w2a[j][cc], p0);
                    p1 = fmaf(h, w2b[j][cc], p1);
                }
            int row  = warp_m * 64 + i * 16 + (lane >> 2) + rh * 8;
            int slot = warp_n * 4 + (lane & 3);
            red[(row * 2 + 0) * 16 + slot] = p0;
            red[(row * 2 + 1) * 16 + slot] = p1;
        }
    }
    __syncthreads();
    {
        int row = tid >> 1, out = tid & 1;
        float s = 0.f;
#pragma unroll
        for (int sl = 0; sl < 16; ++sl) s += red[(row * 2 + out) * 16 + sl];
        g_po[((size_t)(mt * BM + row)) * 8 + nt * 2 + out] = s;
    }
}

// ---------------------------------------------------------------------------
// Reduce partials: o[m,j] = b2[j] + sum_nt po[m,nt,j]
// ---------------------------------------------------------------------------
__global__ void reduce_o_kernel(const float* __restrict__ b2)
{
    int m = blockIdx.x * blockDim.x + threadIdx.x;
    if (m >= MROWS) return;
    const float* p = &g_po[(size_t)m * 8];
    float o0 = b2[0], o1 = b2[1];
#pragma unroll
    for (int nt = 0; nt < 4; ++nt) {
        o0 += p[nt * 2 + 0];
        o1 += p[nt * 2 + 1];
    }
    g_o[(size_t)m * 2 + 0] = o0;
    g_o[(size_t)m * 2 + 1] = o1;
}

// ---------------------------------------------------------------------------
// HMM scan: one block per batch, one thread per chain
// ---------------------------------------------------------------------------
__device__ __forceinline__ float lse2(float a, float b)
{
    float m = fmaxf(a, b);
    float d = fabsf(a - b);
    return m + log1pf(expf(-d));
}

__global__ __launch_bounds__(512)
void scan_kernel(const int* __restrict__ corr,
                 const int* __restrict__ kc,
                 const float* __restrict__ trans_logits,
                 const float* __restrict__ obs_logits,
                 const float* __restrict__ init_logits,
                 float* __restrict__ out)
{
    __shared__ int kcs[TLEN];
    __shared__ int crs[TLEN];
    const int b = blockIdx.x;

    for (int t = threadIdx.x; t < TLEN; t += blockDim.x) {
        kcs[t] = kc[b * TLEN + t];
        crs[t] = corr[b * TLEN + t];
    }
    __syncthreads();

    const int c = threadIdx.x;
    if (c >= NK) return;

    float t00 = trans_logits[c * 4 + 0];
    float t01 = trans_logits[c * 4 + 1];
    float t10 = trans_logits[c * 4 + 2];
    float t11 = trans_logits[c * 4 + 3];
    float ls0 = lse2(t00, t10);
    float ls1 = lse2(t01, t11);
    float lt00 = t00 - ls0, lt10 = t10 - ls0;
    float lt01 = t01 - ls1, lt11 = t11 - ls1;

    float i0 = init_logits[c * 2 + 0];
    float i1 = init_logits[c * 2 + 1];
    float li = lse2(i0, i1);
    float la0 = i0 - li, la1 = i1 - li;

    float ol00 = obs_logits[c * 4 + 0];
    float ol01 = obs_logits[c * 4 + 1];
    float ol10 = obs_logits[c * 4 + 2];
    float ol11 = obs_logits[c * 4 + 3];

    for (int t = 0; t < TLEN; t++) {
        if (kcs[t] == c) {
            const int y = crs[t];
            const size_t idx = (size_t)(b * TLEN + t) * 2;
            float o0 = g_o[idx + 0];
            float o1 = g_o[idx + 1];

            float e00 = ol00 + o0, e01 = ol01 - o0;
            float l0  = lse2(e00, e01);
            float lo00 = e00 - l0, lo01 = e01 - l0;
            float e10 = ol10 + o1, e11 = ol11 - o1;
            float l1  = lse2(e10, e11);
            float lo10 = e10 - l1, lo11 = e11 - l1;

            float py0 = lse2(lo00 + la0, lo10 + la1);
            float py1 = lse2(lo01 + la0, lo11 + la1);
            float pn  = lse2(py0, py1);
            out[idx + 0] = py0 - pn;
            out[idx + 1] = py1 - pn;

            float lp0 = y ? lo01 : lo00;
            float lp1 = y ? lo11 : lo10;
            float na0 = lse2(lp0 + la0 + lt00, lp1 + la1 + lt01);
            float na1 = lse2(lp0 + la0 + lt10, lp1 + la1 + lt11);
            la0 = na0; la1 = na1;
        }
    }
}

// ---------------------------------------------------------------------------
// Launch
// ---------------------------------------------------------------------------
extern "C" void kernel_launch(void* const* d_in, const int* in_sizes, int n_in,
                              void* d_out, int out_size)
{
    const int*   corr = (const int*)  d_in[0];
    const int*   kc   = (const int*)  d_in[1];
    const float* FM   = (const float*)d_in[2];
    const float* W1   = (const float*)d_in[3];
    const float* b1   = (const float*)d_in[4];
    const float* W2   = (const float*)d_in[5];
    const float* b2   = (const float*)d_in[6];
    const float* trl  = (const float*)d_in[7];
    const float* obl  = (const float*)d_in[8];
    const float* inl  = (const float*)d_in[9];
    float* out = (float*)d_out;

    static bool attr_set = false;
    if (!attr_set) {
        cudaFuncSetAttribute(gemm_hmma,
                             cudaFuncAttributeMaxDynamicSharedMemorySize, DYN_SMEM);
        attr_set = true;
    }

    prep_a_kernel<<<(MROWS * NF) / (256 * 4), 256>>>(FM);
    prep_b_kernel<<<(NF * NH) / (256 * 4), 256>>>(W1);

    gemm_hmma<<<dim3(4, MROWS / BM), 256, DYN_SMEM>>>(b1, W2);

    reduce_o_kernel<<<(MROWS + 255) / 256, 256>>>(b2);

    scan_kernel<<<BATCH, 512>>>(corr, kc, trl, obl, inl, out);
}

// round 6
// speedup vs baseline: 3.3631x; 1.7236x over previous
#include <cuda_runtime.h>
#include <cuda_bf16.h>
#include <cuda_fp16.h>
#include <math.h>
#include <stdint.h>

// ---------------------------------------------------------------------------
// Problem constants
// ---------------------------------------------------------------------------
#define BATCH 64
#define TLEN  1024
#define NF    512
#define NH    512
#define NK    500
#define MROWS (BATCH * TLEN)   // 65536

// GEMM config (warp-level HMMA, single-pass fp16, K = 512)
#define BM 128
#define BN 128
#define BK 32                  // fp16 elems per k-chunk
#define KCHUNKS (NF / BK)      // 16
#define STAGES 3

#define A_PITCH 40                     // fp16 elems per smem A row (32 + 8 pad)
#define A_ST_BYTES (BM * A_PITCH * 2)  // 10240
#define B_ST_BYTES (BK * BN * 2)       // 8192
#define ST_BYTES (A_ST_BYTES + B_ST_BYTES)  // 18432
#define DYN_SMEM (STAGES * ST_BYTES)        // 55296

// ---------------------------------------------------------------------------
// Device scratch (static device globals; runtime allocation is forbidden)
// ---------------------------------------------------------------------------
__device__ __align__(16) __half g_A[(size_t)MROWS * NF];   // 64 MB fp16 FM
__device__ __align__(16) __half g_B[(size_t)NF * NH];      // 512 KB fp16 W1
__device__ float g_po[(size_t)MROWS * 4 * 2];              // 2 MB
__device__ float g_o[(size_t)MROWS * 2];                   // 512 KB

// ---------------------------------------------------------------------------
// PTX helpers (all baseline sm_80-era: valid for compute_103 target)
// ---------------------------------------------------------------------------
__device__ __forceinline__ uint32_t smem_u32(const void* p) {
    uint32_t a;
    asm("{ .reg .u64 t; cvta.to.shared.u64 t, %1; cvt.u32.u64 %0, t; }" : "=r"(a) : "l"(p));
    return a;
}
__device__ __forceinline__ void cpa16(uint32_t dst, const void* src) {
    asm volatile("cp.async.cg.shared.global [%0], [%1], 16;" :: "r"(dst), "l"(src));
}
__device__ __forceinline__ void cp_commit() {
    asm volatile("cp.async.commit_group;" ::: "memory");
}
__device__ __forceinline__ void cp_wait1() {
    asm volatile("cp.async.wait_group 1;" ::: "memory");
}
__device__ __forceinline__ void ldm_x4(uint32_t r[4], uint32_t addr) {
    asm volatile("ldmatrix.sync.aligned.m8n8.x4.shared.b16 {%0,%1,%2,%3}, [%4];"
                 : "=r"(r[0]), "=r"(r[1]), "=r"(r[2]), "=r"(r[3]) : "r"(addr));
}
__device__ __forceinline__ void ldm_x4_t(uint32_t& r0, uint32_t& r1, uint32_t& r2,
                                         uint32_t& r3, uint32_t addr) {
    asm volatile("ldmatrix.sync.aligned.m8n8.x4.trans.shared.b16 {%0,%1,%2,%3}, [%4];"
                 : "=r"(r0), "=r"(r1), "=r"(r2), "=r"(r3) : "r"(addr));
}
__device__ __forceinline__ void mma_fp16(float c[4], const uint32_t a[4], const uint32_t b[2]) {
    asm volatile(
        "mma.sync.aligned.m16n8k16.row.col.f32.f16.f16.f32 "
        "{%0,%1,%2,%3}, {%4,%5,%6,%7}, {%8,%9}, {%0,%1,%2,%3};"
        : "+f"(c[0]), "+f"(c[1]), "+f"(c[2]), "+f"(c[3])
        : "r"(a[0]), "r"(a[1]), "r"(a[2]), "r"(a[3]), "r"(b[0]), "r"(b[1]));
}

// ---------------------------------------------------------------------------
// Prep: fp32 -> fp16 (round-to-nearest)
// ---------------------------------------------------------------------------
__global__ void prep_a_kernel(const float* __restrict__ FM)
{
    size_t i = ((size_t)blockIdx.x * 256 + threadIdx.x) * 4;
    float4 v = *(const float4*)(FM + i);
    __half2 p0 = __floats2half2_rn(v.x, v.y);
    __half2 p1 = __floats2half2_rn(v.z, v.w);
    *(__half2*)(g_A + i)     = p0;
    *(__half2*)(g_A + i + 2) = p1;
}

__global__ void prep_b_kernel(const float* __restrict__ W1)
{
    size_t i = ((size_t)blockIdx.x * 256 + threadIdx.x) * 4;
    float4 v = *(const float4*)(W1 + i);
    __half2 p0 = __floats2half2_rn(v.x, v.y);
    __half2 p1 = __floats2half2_rn(v.z, v.w);
    *(__half2*)(g_B + i)     = p0;
    *(__half2*)(g_B + i + 2) = p1;
}

// ---------------------------------------------------------------------------
// GEMM: warp-level fp16 HMMA, 3-stage cp.async pipeline, fused tanh+W2 epilogue
// grid = (4 n-tiles, 512 m-tiles), 256 threads (8 warps: warp_m 0-1, warp_n 0-3)
// ---------------------------------------------------------------------------
extern __shared__ unsigned char dynsmem[];

__device__ __forceinline__ void load_stage(int st, int kc, int mt, int nt,
                                           uint32_t smbase, int tid)
{
    const int k0 = kc * BK;
    const __half* As = g_A + (size_t)mt * BM * NF + k0;
    const __half* Bs = g_B + (size_t)k0 * NH + nt * BN;
    const uint32_t sa = smbase + st * ST_BYTES;
    const uint32_t sb = sa + A_ST_BYTES;
#pragma unroll
    for (int h = 0; h < 2; ++h) {
        int id = tid + h * 256;              // 512 chunks of 16B (A: 128x32 fp16)
        int m  = id >> 2;
        int ca = id & 3;
        cpa16(sa + (uint32_t)m * (A_PITCH * 2) + ca * 16,
              As + (size_t)m * NF + ca * 8);
    }
#pragma unroll
    for (int h = 0; h < 2; ++h) {
        int id = tid + h * 256;              // 512 chunks of 16B (B: 32x128 fp16)
        int k  = id >> 4;
        int cb = id & 15;
        cpa16(sb + ((uint32_t)k * 16 + (cb ^ (k & 7))) * 16,
              Bs + (size_t)k * NH + cb * 8);
    }
}

__global__ __launch_bounds__(256)
void gemm_hmma(const float* __restrict__ b1, const float* __restrict__ W2)
{
    const int tid    = threadIdx.x;
    const int lane   = tid & 31;
    const int wid    = tid >> 5;
    const int warp_m = wid & 1;          // 0..1 -> 64-row halves
    const int warp_n = wid >> 1;         // 0..3 -> 32-col strips
    const int nt     = blockIdx.x;       // 0..3
    const int mt     = blockIdx.y;       // 0..511
    const uint32_t smbase = smem_u32(dynsmem);

    float c[4][4][4];
#pragma unroll
    for (int i = 0; i < 4; ++i)
#pragma unroll
        for (int j = 0; j < 4; ++j)
#pragma unroll
            for (int r = 0; r < 4; ++r) c[i][j][r] = 0.f;

#pragma unroll
    for (int s = 0; s < STAGES - 1; ++s) {
        load_stage(s, s, mt, nt, smbase, tid);
        cp_commit();
    }

    for (int kc = 0; kc < KCHUNKS; ++kc) {
        cp_wait1();
        __syncthreads();

        // prefetch next stage
        const int next = kc + STAGES - 1;
        if (next < KCHUNKS) load_stage(next % STAGES, next, mt, nt, smbase, tid);
        cp_commit();

        const int st = kc % STAGES;
        const uint32_t sa = smbase + st * ST_BYTES;
        const uint32_t sb = sa + A_ST_BYTES;

#pragma unroll
        for (int ks = 0; ks < 2; ++ks) {       // two k16 steps per chunk
            const int k0 = ks * 16;
            uint32_t a[4][4];
#pragma unroll
            for (int i = 0; i < 4; ++i) {
                int m    = warp_m * 64 + i * 16 + (lane & 15);
                int koff = k0 + ((lane >> 4) << 3);
                ldm_x4(a[i], sa + (uint32_t)m * (A_PITCH * 2) + (uint32_t)koff * 2);
            }
            uint32_t b[4][2];
#pragma unroll
            for (int j2 = 0; j2 < 2; ++j2) {   // each x4.trans = two n8 frags
                int k    = k0 + (lane & 15);
                int clog = ((warp_n * 32 + j2 * 16) >> 3) + (lane >> 4);
                uint32_t addr = sb + ((uint32_t)k * 16 + (uint32_t)(clog ^ (k & 7))) * 16;
                uint32_t r0, r1, r2, r3;
                ldm_x4_t(r0, r1, r2, r3, addr);
                b[j2 * 2][0]     = r0; b[j2 * 2][1]     = r1;
                b[j2 * 2 + 1][0] = r2; b[j2 * 2 + 1][1] = r3;
            }
#pragma unroll
            for (int i = 0; i < 4; ++i)
#pragma unroll
                for (int j = 0; j < 4; ++j)
                    mma_fp16(c[i][j], a[i], b[j]);
        }
    }

    // ---- fused epilogue: tanh + W2 projection, partial sums over this n-tile
    __syncthreads();
    float* red = (float*)dynsmem;            // [128 rows][2 outs][16 slots] = 16KB

    float b1v[4][2], w2a[4][2], w2b[4][2];
#pragma unroll
    for (int j = 0; j < 4; ++j)
#pragma unroll
        for (int cc = 0; cc < 2; ++cc) {
            int gn = nt * BN + warp_n * 32 + j * 8 + (lane & 3) * 2 + cc;
            b1v[j][cc] = b1[gn];
            w2a[j][cc] = W2[gn * 2 + 0];
            w2b[j][cc] = W2[gn * 2 + 1];
        }

#pragma unroll
    for (int i = 0; i < 4; ++i) {
#pragma unroll
        for (int rh = 0; rh < 2; ++rh) {
            float p0 = 0.f, p1 = 0.f;
#pragma unroll
            for (int j = 0; j < 4; ++j)
#pragma unroll
                for (int cc = 0; cc < 2; ++cc) {
                    float h = tanhf(c[i][j][rh * 2 + cc] + b1v[j][cc]);
                    p0 = fmaf(h, w2a[j][cc], p0);
                    p1 = fmaf(h, w2b[j][cc], p1);
                }
            int row  = warp_m * 64 + i * 16 + (lane >> 2) + rh * 8;
            int slot = warp_n * 4 + (lane & 3);
            red[(row * 2 + 0) * 16 + slot] = p0;
            red[(row * 2 + 1) * 16 + slot] = p1;
        }
    }
    __syncthreads();
    {
        int row = tid >> 1, out = tid & 1;
        float s = 0.f;
#pragma unroll
        for (int sl = 0; sl < 16; ++sl) s += red[(row * 2 + out) * 16 + sl];
        g_po[((size_t)(mt * BM + row)) * 8 + nt * 2 + out] = s;
    }
}

// ---------------------------------------------------------------------------
// Reduce partials: o[m,j] = b2[j] + sum_nt po[m,nt,j]
// ---------------------------------------------------------------------------
__global__ void reduce_o_kernel(const float* __restrict__ b2)
{
    int m = blockIdx.x * blockDim.x + threadIdx.x;
    if (m >= MROWS) return;
    const float* p = &g_po[(size_t)m * 8];
    float o0 = b2[0], o1 = b2[1];
#pragma unroll
    for (int nt = 0; nt < 4; ++nt) {
        o0 += p[nt * 2 + 0];
        o1 += p[nt * 2 + 1];
    }
    g_o[(size_t)m * 2 + 0] = o0;
    g_o[(size_t)m * 2 + 1] = o1;
}

// ---------------------------------------------------------------------------
// HMM scan: one block per batch, one thread per chain
// ---------------------------------------------------------------------------
__device__ __forceinline__ float lse2(float a, float b)
{
    float m = fmaxf(a, b);
    float d = fabsf(a - b);
    return m + log1pf(expf(-d));
}

__global__ __launch_bounds__(512)
void scan_kernel(const int* __restrict__ corr,
                 const int* __restrict__ kc,
                 const float* __restrict__ trans_logits,
                 const float* __restrict__ obs_logits,
                 const float* __restrict__ init_logits,
                 float* __restrict__ out)
{
    __shared__ int kcs[TLEN];
    __shared__ int crs[TLEN];
    const int b = blockIdx.x;

    for (int t = threadIdx.x; t < TLEN; t += blockDim.x) {
        kcs[t] = kc[b * TLEN + t];
        crs[t] = corr[b * TLEN + t];
    }
    __syncthreads();

    const int c = threadIdx.x;
    if (c >= NK) return;

    float t00 = trans_logits[c * 4 + 0];
    float t01 = trans_logits[c * 4 + 1];
    float t10 = trans_logits[c * 4 + 2];
    float t11 = trans_logits[c * 4 + 3];
    float ls0 = lse2(t00, t10);
    float ls1 = lse2(t01, t11);
    float lt00 = t00 - ls0, lt10 = t10 - ls0;
    float lt01 = t01 - ls1, lt11 = t11 - ls1;

    float i0 = init_logits[c * 2 + 0];
    float i1 = init_logits[c * 2 + 1];
    float li = lse2(i0, i1);
    float la0 = i0 - li, la1 = i1 - li;

    float ol00 = obs_logits[c * 4 + 0];
    float ol01 = obs_logits[c * 4 + 1];
    float ol10 = obs_logits[c * 4 + 2];
    float ol11 = obs_logits[c * 4 + 3];

    for (int t = 0; t < TLEN; t++) {
        if (kcs[t] == c) {
            const int y = crs[t];
            const size_t idx = (size_t)(b * TLEN + t) * 2;
            float o0 = g_o[idx + 0];
            float o1 = g_o[idx + 1];

            float e00 = ol00 + o0, e01 = ol01 - o0;
            float l0  = lse2(e00, e01);
            float lo00 = e00 - l0, lo01 = e01 - l0;
            float e10 = ol10 + o1, e11 = ol11 - o1;
            float l1  = lse2(e10, e11);
            float lo10 = e10 - l1, lo11 = e11 - l1;

            float py0 = lse2(lo00 + la0, lo10 + la1);
            float py1 = lse2(lo01 + la0, lo11 + la1);
            float pn  = lse2(py0, py1);
            out[idx + 0] = py0 - pn;
            out[idx + 1] = py1 - pn;

            float lp0 = y ? lo01 : lo00;
            float lp1 = y ? lo11 : lo10;
            float na0 = lse2(lp0 + la0 + lt00, lp1 + la1 + lt01);
            float na1 = lse2(lp0 + la0 + lt10, lp1 + la1 + lt11);
            la0 = na0; la1 = na1;
        }
    }
}

// ---------------------------------------------------------------------------
// Launch
// ---------------------------------------------------------------------------
extern "C" void kernel_launch(void* const* d_in, const int* in_sizes, int n_in,
                              void* d_out, int out_size)
{
    const int*   corr = (const int*)  d_in[0];
    const int*   kc   = (const int*)  d_in[1];
    const float* FM   = (const float*)d_in[2];
    const float* W1   = (const float*)d_in[3];
    const float* b1   = (const float*)d_in[4];
    const float* W2   = (const float*)d_in[5];
    const float* b2   = (const float*)d_in[6];
    const float* trl  = (const float*)d_in[7];
    const float* obl  = (const float*)d_in[8];
    const float* inl  = (const float*)d_in[9];
    float* out = (float*)d_out;

    static bool attr_set = false;
    if (!attr_set) {
        cudaFuncSetAttribute(gemm_hmma,
                             cudaFuncAttributeMaxDynamicSharedMemorySize, DYN_SMEM);
        attr_set = true;
    }

    prep_a_kernel<<<(MROWS * NF) / (256 * 4), 256>>>(FM);
    prep_b_kernel<<<(NF * NH) / (256 * 4), 256>>>(W1);

    gemm_hmma<<<dim3(4, MROWS / BM), 256, DYN_SMEM>>>(b1, W2);

    reduce_o_kernel<<<(MROWS + 255) / 256, 256>>>(b2);

    scan_kernel<<<BATCH, 512>>>(corr, kc, trl, obl, inl, out);
}

// round 7
// speedup vs baseline: 3.4656x; 1.0305x over previous
#include <cuda_runtime.h>
#include <cuda_bf16.h>
#include <cuda_fp16.h>
#include <math.h>
#include <stdint.h>

// ---------------------------------------------------------------------------
// Problem constants
// ---------------------------------------------------------------------------
#define BATCH 64
#define TLEN  1024
#define NF    512
#define NH    512
#define NK    500
#define MROWS (BATCH * TLEN)   // 65536

// GEMM config (warp-level HMMA, single-pass fp16, K = 512)
#define BM 128
#define BN 256
#define BK 32                  // fp16 elems per k-chunk
#define KCHUNKS (NF / BK)      // 16
#define STAGES 4

#define A_PITCH 40                     // fp16 elems per smem A row (32 + 8 pad)
#define A_ST_BYTES (BM * A_PITCH * 2)  // 10240
#define B_ST_BYTES (BK * BN * 2)       // 16384
#define ST_BYTES (A_ST_BYTES + B_ST_BYTES)  // 26624
#define DYN_SMEM (STAGES * ST_BYTES)        // 106496

// ---------------------------------------------------------------------------
// Device scratch (static device globals; runtime allocation is forbidden)
// ---------------------------------------------------------------------------
__device__ __align__(16) __half g_A[(size_t)MROWS * NF];   // 64 MB fp16 FM
__device__ __align__(16) __half g_B[(size_t)NF * NH];      // 512 KB fp16 W1
__device__ float g_po[(size_t)MROWS * 2 * 2];              // [M][ntile(2)][2]
__device__ float g_o[(size_t)MROWS * 2];                   // unused placeholder

// ---------------------------------------------------------------------------
// PTX helpers (baseline sm_80-era: valid for compute_103 target)
// ---------------------------------------------------------------------------
__device__ __forceinline__ uint32_t smem_u32(const void* p) {
    uint32_t a;
    asm("{ .reg .u64 t; cvta.to.shared.u64 t, %1; cvt.u32.u64 %0, t; }" : "=r"(a) : "l"(p));
    return a;
}
__device__ __forceinline__ void cpa16(uint32_t dst, const void* src) {
    asm volatile("cp.async.cg.shared.global [%0], [%1], 16;" :: "r"(dst), "l"(src));
}
__device__ __forceinline__ void cp_commit() {
    asm volatile("cp.async.commit_group;" ::: "memory");
}
__device__ __forceinline__ void cp_wait2() {
    asm volatile("cp.async.wait_group 2;" ::: "memory");
}
__device__ __forceinline__ void ldm_x4(uint32_t r[4], uint32_t addr) {
    asm volatile("ldmatrix.sync.aligned.m8n8.x4.shared.b16 {%0,%1,%2,%3}, [%4];"
                 : "=r"(r[0]), "=r"(r[1]), "=r"(r[2]), "=r"(r[3]) : "r"(addr));
}
__device__ __forceinline__ void ldm_x4_t(uint32_t& r0, uint32_t& r1, uint32_t& r2,
                                         uint32_t& r3, uint32_t addr) {
    asm volatile("ldmatrix.sync.aligned.m8n8.x4.trans.shared.b16 {%0,%1,%2,%3}, [%4];"
                 : "=r"(r0), "=r"(r1), "=r"(r2), "=r"(r3) : "r"(addr));
}
__device__ __forceinline__ void mma_fp16(float c[4], const uint32_t a[4], const uint32_t b[2]) {
    asm volatile(
        "mma.sync.aligned.m16n8k16.row.col.f32.f16.f16.f32 "
        "{%0,%1,%2,%3}, {%4,%5,%6,%7}, {%8,%9}, {%0,%1,%2,%3};"
        : "+f"(c[0]), "+f"(c[1]), "+f"(c[2]), "+f"(c[3])
        : "r"(a[0]), "r"(a[1]), "r"(a[2]), "r"(a[3]), "r"(b[0]), "r"(b[1]));
}

// ---------------------------------------------------------------------------
// Prep: fp32 -> fp16 (round-to-nearest)
// ---------------------------------------------------------------------------
__global__ void prep_a_kernel(const float* __restrict__ FM)
{
    size_t i = ((size_t)blockIdx.x * 256 + threadIdx.x) * 4;
    float4 v = *(const float4*)(FM + i);
    *(__half2*)(g_A + i)     = __floats2half2_rn(v.x, v.y);
    *(__half2*)(g_A + i + 2) = __floats2half2_rn(v.z, v.w);
}

__global__ void prep_b_kernel(const float* __restrict__ W1)
{
    size_t i = ((size_t)blockIdx.x * 256 + threadIdx.x) * 4;
    float4 v = *(const float4*)(W1 + i);
    *(__half2*)(g_B + i)     = __floats2half2_rn(v.x, v.y);
    *(__half2*)(g_B + i + 2) = __floats2half2_rn(v.z, v.w);
}

// ---------------------------------------------------------------------------
// GEMM: warp-level fp16 HMMA, 4-stage cp.async pipeline, fused tanh+W2 epilogue
// grid = (2 n-tiles, 512 m-tiles), 256 threads (8 warps: warp_m 0-1, warp_n 0-3)
// warp tile = 64 rows x 64 cols
// ---------------------------------------------------------------------------
extern __shared__ unsigned char dynsmem[];

__device__ __forceinline__ void load_stage(int st, int kc, int mt, int nt,
                                           uint32_t smbase, int tid)
{
    const int k0 = kc * BK;
    const __half* As = g_A + (size_t)mt * BM * NF + k0;
    const __half* Bs = g_B + (size_t)k0 * NH + nt * BN;
    const uint32_t sa = smbase + st * ST_BYTES;
    const uint32_t sb = sa + A_ST_BYTES;
    // A: 128x32 fp16 = 512 chunks of 16B
#pragma unroll
    for (int h = 0; h < 2; ++h) {
        int id = tid + h * 256;
        int m  = id >> 2;
        int ca = id & 3;
        cpa16(sa + (uint32_t)m * (A_PITCH * 2) + ca * 16,
              As + (size_t)m * NF + ca * 8);
    }
    // B: 32x256 fp16 = 1024 chunks of 16B; 32 chunks per k-row, XOR-swizzled
#pragma unroll
    for (int h = 0; h < 4; ++h) {
        int id = tid + h * 256;
        int k  = id >> 5;
        int cb = id & 31;
        cpa16(sb + ((uint32_t)k * 32 + (uint32_t)(cb ^ (k & 7))) * 16,
              Bs + (size_t)k * NH + cb * 8);
    }
}

__global__ __launch_bounds__(256, 1)
void gemm_hmma(const float* __restrict__ b1, const float* __restrict__ W2)
{
    const int tid    = threadIdx.x;
    const int lane   = tid & 31;
    const int wid    = tid >> 5;
    const int warp_m = wid & 1;          // 0..1 -> 64-row halves
    const int warp_n = wid >> 1;         // 0..3 -> 64-col strips
    const int nt     = blockIdx.x;       // 0..1
    const int mt     = blockIdx.y;       // 0..511
    const uint32_t smbase = smem_u32(dynsmem);

    float c[4][8][4];
#pragma unroll
    for (int i = 0; i < 4; ++i)
#pragma unroll
        for (int j = 0; j < 8; ++j)
#pragma unroll
            for (int r = 0; r < 4; ++r) c[i][j][r] = 0.f;

#pragma unroll
    for (int s = 0; s < STAGES - 1; ++s) {
        load_stage(s, s, mt, nt, smbase, tid);
        cp_commit();
    }

    for (int kc = 0; kc < KCHUNKS; ++kc) {
        cp_wait2();
        __syncthreads();

        const int next = kc + STAGES - 1;
        if (next < KCHUNKS) load_stage(next & (STAGES - 1), next, mt, nt, smbase, tid);
        cp_commit();

        const int st = kc & (STAGES - 1);
        const uint32_t sa = smbase + st * ST_BYTES;
        const uint32_t sb = sa + A_ST_BYTES;

#pragma unroll
        for (int ks = 0; ks < 2; ++ks) {       // two k16 steps per chunk
            const int k0 = ks * 16;
            uint32_t a[4][4];
#pragma unroll
            for (int i = 0; i < 4; ++i) {
                int m    = warp_m * 64 + i * 16 + (lane & 15);
                int koff = k0 + ((lane >> 4) << 3);
                ldm_x4(a[i], sa + (uint32_t)m * (A_PITCH * 2) + (uint32_t)koff * 2);
            }
            uint32_t b[8][2];
#pragma unroll
            for (int j2 = 0; j2 < 4; ++j2) {   // each x4.trans = two n8 frags
                int k    = k0 + (lane & 15);
                int clog = ((warp_n * 64 + j2 * 16) >> 3) + (lane >> 4);
                uint32_t addr = sb + ((uint32_t)k * 32 + (uint32_t)(clog ^ (k & 7))) * 16;
                uint32_t r0, r1, r2, r3;
                ldm_x4_t(r0, r1, r2, r3, addr);
                b[j2 * 2][0]     = r0; b[j2 * 2][1]     = r1;
                b[j2 * 2 + 1][0] = r2; b[j2 * 2 + 1][1] = r3;
            }
#pragma unroll
            for (int i = 0; i < 4; ++i)
#pragma unroll
                for (int j = 0; j < 8; ++j)
                    mma_fp16(c[i][j], a[i], b[j]);
        }
    }

    // ---- fused epilogue: tanh + W2 projection, partial sums over this n-tile
    __syncthreads();
    float* red = (float*)dynsmem;            // [128 rows][2 outs][16 slots] = 16KB

    float b1v[8][2], w2a[8][2], w2b[8][2];
#pragma unroll
    for (int j = 0; j < 8; ++j)
#pragma unroll
        for (int cc = 0; cc < 2; ++cc) {
            int gn = nt * BN + warp_n * 64 + j * 8 + (lane & 3) * 2 + cc;
            b1v[j][cc] = b1[gn];
            w2a[j][cc] = W2[gn * 2 + 0];
            w2b[j][cc] = W2[gn * 2 + 1];
        }

#pragma unroll
    for (int i = 0; i < 4; ++i) {
#pragma unroll
        for (int rh = 0; rh < 2; ++rh) {
            float p0 = 0.f, p1 = 0.f;
#pragma unroll
            for (int j = 0; j < 8; ++j)
#pragma unroll
                for (int cc = 0; cc < 2; ++cc) {
                    float h = tanhf(c[i][j][rh * 2 + cc] + b1v[j][cc]);
                    p0 = fmaf(h, w2a[j][cc], p0);
                    p1 = fmaf(h, w2b[j][cc], p1);
                }
            int row  = warp_m * 64 + i * 16 + (lane >> 2) + rh * 8;
            int slot = warp_n * 4 + (lane & 3);
            red[(row * 2 + 0) * 16 + slot] = p0;
            red[(row * 2 + 1) * 16 + slot] = p1;
        }
    }
    __syncthreads();
    {
        int row = tid >> 1, out = tid & 1;
        float s = 0.f;
#pragma unroll
        for (int sl = 0; sl < 16; ++sl) s += red[(row * 2 + out) * 16 + sl];
        g_po[((size_t)(mt * BM + row)) * 4 + nt * 2 + out] = s;
    }
}

// ---------------------------------------------------------------------------
// HMM scan: one block per batch, one thread per chain.
// Sums the 2 n-block GEMM partials + b2 inline (no reduce kernel).
// ---------------------------------------------------------------------------
__device__ __forceinline__ float lse2(float a, float b)
{
    float m = fmaxf(a, b);
    float d = fabsf(a - b);
    return m + log1pf(expf(-d));
}

__global__ __launch_bounds__(512)
void scan_kernel(const int* __restrict__ corr,
                 const int* __restrict__ kc,
                 const float* __restrict__ trans_logits,
                 const float* __restrict__ obs_logits,
                 const float* __restrict__ init_logits,
                 const float* __restrict__ b2,
                 float* __restrict__ out)
{
    __shared__ int kcs[TLEN];
    __shared__ int crs[TLEN];
    __shared__ float s_b2[2];
    const int b = blockIdx.x;

    for (int t = threadIdx.x; t < TLEN; t += blockDim.x) {
        kcs[t] = kc[b * TLEN + t];
        crs[t] = corr[b * TLEN + t];
    }
    if (threadIdx.x < 2) s_b2[threadIdx.x] = b2[threadIdx.x];
    __syncthreads();

    const int c = threadIdx.x;
    if (c >= NK) return;

    float t00 = trans_logits[c * 4 + 0];
    float t01 = trans_logits[c * 4 + 1];
    float t10 = trans_logits[c * 4 + 2];
    float t11 = trans_logits[c * 4 + 3];
    float ls0 = lse2(t00, t10);
    float ls1 = lse2(t01, t11);
    float lt00 = t00 - ls0, lt10 = t10 - ls0;
    float lt01 = t01 - ls1, lt11 = t11 - ls1;

    float i0 = init_logits[c * 2 + 0];
    float i1 = init_logits[c * 2 + 1];
    float li = lse2(i0, i1);
    float la0 = i0 - li, la1 = i1 - li;

    float ol00 = obs_logits[c * 4 + 0];
    float ol01 = obs_logits[c * 4 + 1];
    float ol10 = obs_logits[c * 4 + 2];
    float ol11 = obs_logits[c * 4 + 3];

    const float bb0 = s_b2[0], bb1 = s_b2[1];

    for (int t = 0; t < TLEN; t++) {
        if (kcs[t] == c) {
            const int y = crs[t];
            const size_t m = (size_t)(b * TLEN + t);
            float4 po = *(const float4*)&g_po[m * 4];
            float o0 = bb0 + po.x + po.z;
            float o1 = bb1 + po.y + po.w;

            float e00 = ol00 + o0, e01 = ol01 - o0;
            float l0  = lse2(e00, e01);
            float lo00 = e00 - l0, lo01 = e01 - l0;
            float e10 = ol10 + o1, e11 = ol11 - o1;
            float l1  = lse2(e10, e11);
            float lo10 = e10 - l1, lo11 = e11 - l1;

            float py0 = lse2(lo00 + la0, lo10 + la1);
            float py1 = lse2(lo01 + la0, lo11 + la1);
            float pn  = lse2(py0, py1);
            out[m * 2 + 0] = py0 - pn;
            out[m * 2 + 1] = py1 - pn;

            float lp0 = y ? lo01 : lo00;
            float lp1 = y ? lo11 : lo10;
            float na0 = lse2(lp0 + la0 + lt00, lp1 + la1 + lt01);
            float na1 = lse2(lp0 + la0 + lt10, lp1 + la1 + lt11);
            la0 = na0; la1 = na1;
        }
    }
}

// ---------------------------------------------------------------------------
// Launch
// ---------------------------------------------------------------------------
extern "C" void kernel_launch(void* const* d_in, const int* in_sizes, int n_in,
                              void* d_out, int out_size)
{
    const int*   corr = (const int*)  d_in[0];
    const int*   kc   = (const int*)  d_in[1];
    const float* FM   = (const float*)d_in[2];
    const float* W1   = (const float*)d_in[3];
    const float* b1   = (const float*)d_in[4];
    const float* W2   = (const float*)d_in[5];
    const float* b2   = (const float*)d_in[6];
    const float* trl  = (const float*)d_in[7];
    const float* obl  = (const float*)d_in[8];
    const float* inl  = (const float*)d_in[9];
    float* out = (float*)d_out;

    static bool attr_set = false;
    if (!attr_set) {
        cudaFuncSetAttribute(gemm_hmma,
                             cudaFuncAttributeMaxDynamicSharedMemorySize, DYN_SMEM);
        attr_set = true;
    }

    prep_a_kernel<<<(MROWS * NF) / (256 * 4), 256>>>(FM);
    prep_b_kernel<<<(NF * NH) / (256 * 4), 256>>>(W1);

    gemm_hmma<<<dim3(2, MROWS / BM), 256, DYN_SMEM>>>(b1, W2);

    scan_kernel<<<BATCH, 512>>>(corr, kc, trl, obl, inl, b2, out);
}

// round 8
// speedup vs baseline: 3.6931x; 1.0656x over previous
#include <cuda_runtime.h>
#include <cuda_bf16.h>
#include <cuda_fp16.h>
#include <math.h>
#include <stdint.h>

// ---------------------------------------------------------------------------
// Problem constants
// ---------------------------------------------------------------------------
#define BATCH 64
#define TLEN  1024
#define NF    512
#define NH    512
#define NK    500
#define MROWS (BATCH * TLEN)   // 65536

// GEMM config (warp-level HMMA, single-pass fp16, K = 512)
#define BM 128
#define BN 256
#define BK 32                  // fp16 elems per k-chunk
#define KCHUNKS (NF / BK)      // 16
#define STAGES 4

#define A_PITCH 40                     // fp16 elems per smem A row (32 + 8 pad)
#define A_ST_BYTES (BM * A_PITCH * 2)  // 10240
#define B_ST_BYTES (BK * BN * 2)       // 16384
#define ST_BYTES (A_ST_BYTES + B_ST_BYTES)  // 26624
#define DYN_SMEM (STAGES * ST_BYTES)        // 106496

// Scan config
#define CB 4                   // chain-blocks per batch
#define SCAN_THREADS 128       // chains per block

// ---------------------------------------------------------------------------
// Device scratch (static device globals; runtime allocation is forbidden)
// ---------------------------------------------------------------------------
__device__ __align__(16) __half g_A[(size_t)MROWS * NF];   // 64 MB fp16 FM
__device__ __align__(16) __half g_B[(size_t)NF * NH];      // 512 KB fp16 W1
__device__ float g_po[(size_t)MROWS * 2 * 2];              // [M][ntile(2)][2]

// ---------------------------------------------------------------------------
// PTX helpers (baseline sm_80-era: valid for compute_103 target)
// ---------------------------------------------------------------------------
__device__ __forceinline__ uint32_t smem_u32(const void* p) {
    uint32_t a;
    asm("{ .reg .u64 t; cvta.to.shared.u64 t, %1; cvt.u32.u64 %0, t; }" : "=r"(a) : "l"(p));
    return a;
}
__device__ __forceinline__ void cpa16(uint32_t dst, const void* src) {
    asm volatile("cp.async.cg.shared.global [%0], [%1], 16;" :: "r"(dst), "l"(src));
}
__device__ __forceinline__ void cp_commit() {
    asm volatile("cp.async.commit_group;" ::: "memory");
}
__device__ __forceinline__ void cp_wait2() {
    asm volatile("cp.async.wait_group 2;" ::: "memory");
}
__device__ __forceinline__ void ldm_x4(uint32_t r[4], uint32_t addr) {
    asm volatile("ldmatrix.sync.aligned.m8n8.x4.shared.b16 {%0,%1,%2,%3}, [%4];"
                 : "=r"(r[0]), "=r"(r[1]), "=r"(r[2]), "=r"(r[3]) : "r"(addr));
}
__device__ __forceinline__ void ldm_x4_t(uint32_t& r0, uint32_t& r1, uint32_t& r2,
                                         uint32_t& r3, uint32_t addr) {
    asm volatile("ldmatrix.sync.aligned.m8n8.x4.trans.shared.b16 {%0,%1,%2,%3}, [%4];"
                 : "=r"(r0), "=r"(r1), "=r"(r2), "=r"(r3) : "r"(addr));
}
__device__ __forceinline__ void mma_fp16(float c[4], const uint32_t a[4], const uint32_t b[2]) {
    asm volatile(
        "mma.sync.aligned.m16n8k16.row.col.f32.f16.f16.f32 "
        "{%0,%1,%2,%3}, {%4,%5,%6,%7}, {%8,%9}, {%0,%1,%2,%3};"
        : "+f"(c[0]), "+f"(c[1]), "+f"(c[2]), "+f"(c[3])
        : "r"(a[0]), "r"(a[1]), "r"(a[2]), "r"(a[3]), "r"(b[0]), "r"(b[1]));
}

// ---------------------------------------------------------------------------
// Prep: fp32 -> fp16 (round-to-nearest)
// ---------------------------------------------------------------------------
__global__ void prep_a_kernel(const float* __restrict__ FM)
{
    size_t i = ((size_t)blockIdx.x * 256 + threadIdx.x) * 4;
    float4 v = *(const float4*)(FM + i);
    *(__half2*)(g_A + i)     = __floats2half2_rn(v.x, v.y);
    *(__half2*)(g_A + i + 2) = __floats2half2_rn(v.z, v.w);
}

__global__ void prep_b_kernel(const float* __restrict__ W1)
{
    size_t i = ((size_t)blockIdx.x * 256 + threadIdx.x) * 4;
    float4 v = *(const float4*)(W1 + i);
    *(__half2*)(g_B + i)     = __floats2half2_rn(v.x, v.y);
    *(__half2*)(g_B + i + 2) = __floats2half2_rn(v.z, v.w);
}

// ---------------------------------------------------------------------------
// GEMM: warp-level fp16 HMMA, 4-stage cp.async pipeline, fused tanh+W2 epilogue
// grid = (2 n-tiles, 512 m-tiles), 256 threads (8 warps: warp_m 0-1, warp_n 0-3)
// ---------------------------------------------------------------------------
extern __shared__ unsigned char dynsmem[];

__device__ __forceinline__ void load_stage(int st, int kc, int mt, int nt,
                                           uint32_t smbase, int tid)
{
    const int k0 = kc * BK;
    const __half* As = g_A + (size_t)mt * BM * NF + k0;
    const __half* Bs = g_B + (size_t)k0 * NH + nt * BN;
    const uint32_t sa = smbase + st * ST_BYTES;
    const uint32_t sb = sa + A_ST_BYTES;
#pragma unroll
    for (int h = 0; h < 2; ++h) {
        int id = tid + h * 256;
        int m  = id >> 2;
        int ca = id & 3;
        cpa16(sa + (uint32_t)m * (A_PITCH * 2) + ca * 16,
              As + (size_t)m * NF + ca * 8);
    }
#pragma unroll
    for (int h = 0; h < 4; ++h) {
        int id = tid + h * 256;
        int k  = id >> 5;
        int cb = id & 31;
        cpa16(sb + ((uint32_t)k * 32 + (uint32_t)(cb ^ (k & 7))) * 16,
              Bs + (size_t)k * NH + cb * 8);
    }
}

__global__ __launch_bounds__(256, 1)
void gemm_hmma(const float* __restrict__ b1, const float* __restrict__ W2)
{
    const int tid    = threadIdx.x;
    const int lane   = tid & 31;
    const int wid    = tid >> 5;
    const int warp_m = wid & 1;
    const int warp_n = wid >> 1;
    const int nt     = blockIdx.x;
    const int mt     = blockIdx.y;
    const uint32_t smbase = smem_u32(dynsmem);

    float c[4][8][4];
#pragma unroll
    for (int i = 0; i < 4; ++i)
#pragma unroll
        for (int j = 0; j < 8; ++j)
#pragma unroll
            for (int r = 0; r < 4; ++r) c[i][j][r] = 0.f;

#pragma unroll
    for (int s = 0; s < STAGES - 1; ++s) {
        load_stage(s, s, mt, nt, smbase, tid);
        cp_commit();
    }

    for (int kc = 0; kc < KCHUNKS; ++kc) {
        cp_wait2();
        __syncthreads();

        const int next = kc + STAGES - 1;
        if (next < KCHUNKS) load_stage(next & (STAGES - 1), next, mt, nt, smbase, tid);
        cp_commit();

        const int st = kc & (STAGES - 1);
        const uint32_t sa = smbase + st * ST_BYTES;
        const uint32_t sb = sa + A_ST_BYTES;

#pragma unroll
        for (int ks = 0; ks < 2; ++ks) {
            const int k0 = ks * 16;
            uint32_t a[4][4];
#pragma unroll
            for (int i = 0; i < 4; ++i) {
                int m    = warp_m * 64 + i * 16 + (lane & 15);
                int koff = k0 + ((lane >> 4) << 3);
                ldm_x4(a[i], sa + (uint32_t)m * (A_PITCH * 2) + (uint32_t)koff * 2);
            }
            uint32_t b[8][2];
#pragma unroll
            for (int j2 = 0; j2 < 4; ++j2) {
                int k    = k0 + (lane & 15);
                int clog = ((warp_n * 64 + j2 * 16) >> 3) + (lane >> 4);
                uint32_t addr = sb + ((uint32_t)k * 32 + (uint32_t)(clog ^ (k & 7))) * 16;
                uint32_t r0, r1, r2, r3;
                ldm_x4_t(r0, r1, r2, r3, addr);
                b[j2 * 2][0]     = r0; b[j2 * 2][1]     = r1;
                b[j2 * 2 + 1][0] = r2; b[j2 * 2 + 1][1] = r3;
            }
#pragma unroll
            for (int i = 0; i < 4; ++i)
#pragma unroll
                for (int j = 0; j < 8; ++j)
                    mma_fp16(c[i][j], a[i], b[j]);
        }
    }

    __syncthreads();
    float* red = (float*)dynsmem;

    float b1v[8][2], w2a[8][2], w2b[8][2];
#pragma unroll
    for (int j = 0; j < 8; ++j)
#pragma unroll
        for (int cc = 0; cc < 2; ++cc) {
            int gn = nt * BN + warp_n * 64 + j * 8 + (lane & 3) * 2 + cc;
            b1v[j][cc] = b1[gn];
            w2a[j][cc] = W2[gn * 2 + 0];
            w2b[j][cc] = W2[gn * 2 + 1];
        }

#pragma unroll
    for (int i = 0; i < 4; ++i) {
#pragma unroll
        for (int rh = 0; rh < 2; ++rh) {
            float p0 = 0.f, p1 = 0.f;
#pragma unroll
            for (int j = 0; j < 8; ++j)
#pragma unroll
                for (int cc = 0; cc < 2; ++cc) {
                    float h = tanhf(c[i][j][rh * 2 + cc] + b1v[j][cc]);
                    p0 = fmaf(h, w2a[j][cc], p0);
                    p1 = fmaf(h, w2b[j][cc], p1);
                }
            int row  = warp_m * 64 + i * 16 + (lane >> 2) + rh * 8;
            int slot = warp_n * 4 + (lane & 3);
            red[(row * 2 + 0) * 16 + slot] = p0;
            red[(row * 2 + 1) * 16 + slot] = p1;
        }
    }
    __syncthreads();
    {
        int row = tid >> 1, out = tid & 1;
        float s = 0.f;
#pragma unroll
        for (int sl = 0; sl < 16; ++sl) s += red[(row * 2 + out) * 16 + sl];
        g_po[((size_t)(mt * BM + row)) * 4 + nt * 2 + out] = s;
    }
}

// ---------------------------------------------------------------------------
// HMM scan v2: grid (BATCH, CB), 128 threads; thread owns chain
// c = cb*128 + tid. Packed combo[t] = kc*2+corr in smem (uint16), fast-skip
// loop checks 4 timesteps per iteration via __vcmpeq2.
// ---------------------------------------------------------------------------
__device__ __forceinline__ float lse2(float a, float b)
{
    float m = fmaxf(a, b);
    float d = fabsf(a - b);
    return m + log1pf(expf(-d));
}

__global__ __launch_bounds__(SCAN_THREADS)
void scan_kernel(const int* __restrict__ corr,
                 const int* __restrict__ kc,
                 const float* __restrict__ trans_logits,
                 const float* __restrict__ obs_logits,
                 const float* __restrict__ init_logits,
                 const float* __restrict__ b2,
                 float* __restrict__ out)
{
    __shared__ __align__(8) uint16_t combo[TLEN];
    __shared__ float s_b2[2];
    const int b  = blockIdx.x;
    const int cb = blockIdx.y;

    for (int t = threadIdx.x; t < TLEN; t += SCAN_THREADS) {
        combo[t] = (uint16_t)((kc[b * TLEN + t] << 1) | corr[b * TLEN + t]);
    }
    if (threadIdx.x < 2) s_b2[threadIdx.x] = b2[threadIdx.x];
    __syncthreads();

    const int c = cb * SCAN_THREADS + threadIdx.x;
    if (c >= NK) return;

    float t00 = trans_logits[c * 4 + 0];
    float t01 = trans_logits[c * 4 + 1];
    float t10 = trans_logits[c * 4 + 2];
    float t11 = trans_logits[c * 4 + 3];
    float ls0 = lse2(t00, t10);
    float ls1 = lse2(t01, t11);
    float lt00 = t00 - ls0, lt10 = t10 - ls0;
    float lt01 = t01 - ls1, lt11 = t11 - ls1;

    float i0 = init_logits[c * 2 + 0];
    float i1 = init_logits[c * 2 + 1];
    float li = lse2(i0, i1);
    float la0 = i0 - li, la1 = i1 - li;

    float ol00 = obs_logits[c * 4 + 0];
    float ol01 = obs_logits[c * 4 + 1];
    float ol10 = obs_logits[c * 4 + 2];
    float ol11 = obs_logits[c * 4 + 3];

    const float bb0 = s_b2[0], bb1 = s_b2[1];
    const uint32_t c2   = (uint32_t)(c << 1);
    const uint32_t key2 = (c2 << 16) | c2;

    for (int t4 = 0; t4 < TLEN; t4 += 4) {
        uint2 v = *(const uint2*)&combo[t4];      // 4 packed uint16
        uint32_t m0 = __vcmpeq2(v.x & 0xFFFEFFFEu, key2);
        uint32_t m1 = __vcmpeq2(v.y & 0xFFFEFFFEu, key2);
        if ((m0 | m1) == 0u) continue;

#pragma unroll
        for (int q = 0; q < 4; ++q) {
            uint32_t cv = (q < 2) ? ((q == 0) ? (v.x & 0xFFFFu) : (v.x >> 16))
                                  : ((q == 2) ? (v.y & 0xFFFFu) : (v.y >> 16));
            if ((cv >> 1) != (uint32_t)c) continue;
            const int y = (int)(cv & 1u);
            const size_t m = (size_t)(b * TLEN + t4 + q);
            float4 po = *(const float4*)&g_po[m * 4];
            float o0 = bb0 + po.x + po.z;
            float o1 = bb1 + po.y + po.w;

            float e00 = ol00 + o0, e01 = ol01 - o0;
            float l0  = lse2(e00, e01);
            float lo00 = e00 - l0, lo01 = e01 - l0;
            float e10 = ol10 + o1, e11 = ol11 - o1;
            float l1  = lse2(e10, e11);
            float lo10 = e10 - l1, lo11 = e11 - l1;

            float py0 = lse2(lo00 + la0, lo10 + la1);
            float py1 = lse2(lo01 + la0, lo11 + la1);
            float pn  = lse2(py0, py1);
            out[m * 2 + 0] = py0 - pn;
            out[m * 2 + 1] = py1 - pn;

            float lp0 = y ? lo01 : lo00;
            float lp1 = y ? lo11 : lo10;
            float na0 = lse2(lp0 + la0 + lt00, lp1 + la1 + lt01);
            float na1 = lse2(lp0 + la0 + lt10, lp1 + la1 + lt11);
            la0 = na0; la1 = na1;
        }
    }
}

// ---------------------------------------------------------------------------
// Launch
// ---------------------------------------------------------------------------
extern "C" void kernel_launch(void* const* d_in, const int* in_sizes, int n_in,
                              void* d_out, int out_size)
{
    const int*   corr = (const int*)  d_in[0];
    const int*   kc   = (const int*)  d_in[1];
    const float* FM   = (const float*)d_in[2];
    const float* W1   = (const float*)d_in[3];
    const float* b1   = (const float*)d_in[4];
    const float* W2   = (const float*)d_in[5];
    const float* b2   = (const float*)d_in[6];
    const float* trl  = (const float*)d_in[7];
    const float* obl  = (const float*)d_in[8];
    const float* inl  = (const float*)d_in[9];
    float* out = (float*)d_out;

    static bool attr_set = false;
    if (!attr_set) {
        cudaFuncSetAttribute(gemm_hmma,
                             cudaFuncAttributeMaxDynamicSharedMemorySize, DYN_SMEM);
        attr_set = true;
    }

    prep_a_kernel<<<(MROWS * NF) / (256 * 4), 256>>>(FM);
    prep_b_kernel<<<(NF * NH) / (256 * 4), 256>>>(W1);

    gemm_hmma<<<dim3(2, MROWS / BM), 256, DYN_SMEM>>>(b1, W2);

    scan_kernel<<<dim3(BATCH, CB), SCAN_THREADS>>>(corr, kc, trl, obl, inl, b2, out);
}

// round 9
// speedup vs baseline: 5.1299x; 1.3890x over previous
#include <cuda_runtime.h>
#include <cuda_bf16.h>
#include <cuda_fp16.h>
#include <math.h>
#include <stdint.h>

// ---------------------------------------------------------------------------
// Problem constants
// ---------------------------------------------------------------------------
#define BATCH 64
#define TLEN  1024
#define NF    512
#define NH    512
#define NK    500
#define NKP   512              // padded chain count (pow2 for scan)
#define MROWS (BATCH * TLEN)   // 65536

// GEMM config (warp-level HMMA, single-pass fp16, K = 512)
#define BM 128
#define BN 256
#define BK 32
#define KCHUNKS (NF / BK)      // 16
#define STAGES 4

#define A_PITCH 40
#define A_ST_BYTES (BM * A_PITCH * 2)       // 10240
#define B_ST_BYTES (BK * BN * 2)            // 16384
#define ST_BYTES (A_ST_BYTES + B_ST_BYTES)  // 26624
#define DYN_SMEM (STAGES * ST_BYTES)        // 106496

// ---------------------------------------------------------------------------
// Device scratch (static device globals; runtime allocation is forbidden)
// ---------------------------------------------------------------------------
__device__ __align__(16) __half g_A[(size_t)MROWS * NF];   // 64 MB fp16 FM
__device__ __align__(16) __half g_B[(size_t)NF * NH];      // 512 KB fp16 W1
__device__ float g_po[(size_t)MROWS * 2 * 2];              // [M][ntile(2)][2]
__device__ int      g_vstart[BATCH * (NKP + 1)];           // per-batch chain segment starts
__device__ uint32_t g_visits[BATCH * TLEN];                // (t<<1)|y per visit

// ---------------------------------------------------------------------------
// PTX helpers
// ---------------------------------------------------------------------------
__device__ __forceinline__ uint32_t smem_u32(const void* p) {
    uint32_t a;
    asm("{ .reg .u64 t; cvta.to.shared.u64 t, %1; cvt.u32.u64 %0, t; }" : "=r"(a) : "l"(p));
    return a;
}
__device__ __forceinline__ void cpa16(uint32_t dst, const void* src) {
    asm volatile("cp.async.cg.shared.global [%0], [%1], 16;" :: "r"(dst), "l"(src));
}
__device__ __forceinline__ void cp_commit() {
    asm volatile("cp.async.commit_group;" ::: "memory");
}
__device__ __forceinline__ void cp_wait2() {
    asm volatile("cp.async.wait_group 2;" ::: "memory");
}
__device__ __forceinline__ void ldm_x4(uint32_t r[4], uint32_t addr) {
    asm volatile("ldmatrix.sync.aligned.m8n8.x4.shared.b16 {%0,%1,%2,%3}, [%4];"
                 : "=r"(r[0]), "=r"(r[1]), "=r"(r[2]), "=r"(r[3]) : "r"(addr));
}
__device__ __forceinline__ void ldm_x4_t(uint32_t& r0, uint32_t& r1, uint32_t& r2,
                                         uint32_t& r3, uint32_t addr) {
    asm volatile("ldmatrix.sync.aligned.m8n8.x4.trans.shared.b16 {%0,%1,%2,%3}, [%4];"
                 : "=r"(r0), "=r"(r1), "=r"(r2), "=r"(r3) : "r"(addr));
}
__device__ __forceinline__ void mma_fp16(float c[4], const uint32_t a[4], const uint32_t b[2]) {
    asm volatile(
        "mma.sync.aligned.m16n8k16.row.col.f32.f16.f16.f32 "
        "{%0,%1,%2,%3}, {%4,%5,%6,%7}, {%8,%9}, {%0,%1,%2,%3};"
        : "+f"(c[0]), "+f"(c[1]), "+f"(c[2]), "+f"(c[3])
        : "r"(a[0]), "r"(a[1]), "r"(a[2]), "r"(a[3]), "r"(b[0]), "r"(b[1]));
}

// ---------------------------------------------------------------------------
// Prep: fp32 -> fp16
// ---------------------------------------------------------------------------
__global__ void prep_a_kernel(const float* __restrict__ FM)
{
    size_t i = ((size_t)blockIdx.x * 256 + threadIdx.x) * 4;
    float4 v = *(const float4*)(FM + i);
    *(__half2*)(g_A + i)     = __floats2half2_rn(v.x, v.y);
    *(__half2*)(g_A + i + 2) = __floats2half2_rn(v.z, v.w);
}

__global__ void prep_b_kernel(const float* __restrict__ W1)
{
    size_t i = ((size_t)blockIdx.x * 256 + threadIdx.x) * 4;
    float4 v = *(const float4*)(W1 + i);
    *(__half2*)(g_B + i)     = __floats2half2_rn(v.x, v.y);
    *(__half2*)(g_B + i + 2) = __floats2half2_rn(v.z, v.w);
}

// ---------------------------------------------------------------------------
// Visit-list construction: per-batch counting sort of timesteps by chain.
// ---------------------------------------------------------------------------
__global__ __launch_bounds__(512)
void build_visits_kernel(const int* __restrict__ corr, const int* __restrict__ kc)
{
    __shared__ int cnt[NKP];
    __shared__ int scan_buf[NKP];
    __shared__ int pos[NKP];
    const int b   = blockIdx.x;
    const int tid = threadIdx.x;

    cnt[tid] = 0;
    __syncthreads();

#pragma unroll
    for (int h = 0; h < 2; ++h) {
        int t = tid + h * 512;
        atomicAdd(&cnt[kc[b * TLEN + t]], 1);
    }
    __syncthreads();

    // Hillis-Steele inclusive scan over 512 entries -> exclusive starts
    int v = cnt[tid];
    scan_buf[tid] = v;
    __syncthreads();
#pragma unroll
    for (int off = 1; off < NKP; off <<= 1) {
        int add = (tid >= off) ? scan_buf[tid - off] : 0;
        __syncthreads();
        scan_buf[tid] += add;
        __syncthreads();
    }
    int start = scan_buf[tid] - v;   // exclusive
    pos[tid] = start;
    g_vstart[b * (NKP + 1) + tid] = start;
    if (tid == NKP - 1) g_vstart[b * (NKP + 1) + NKP] = TLEN;
    __syncthreads();

    // scatter (order within a chain arbitrary; consumer sorts by t)
#pragma unroll
    for (int h = 0; h < 2; ++h) {
        int t = tid + h * 512;
        int c = kc[b * TLEN + t];
        int slot = atomicAdd(&pos[c], 1);
        g_visits[b * TLEN + slot] = ((uint32_t)t << 1) | (uint32_t)corr[b * TLEN + t];
    }
}

// ---------------------------------------------------------------------------
// GEMM: warp-level fp16 HMMA, 4-stage cp.async pipeline, fused tanh+W2 epilogue
// ---------------------------------------------------------------------------
extern __shared__ unsigned char dynsmem[];

__device__ __forceinline__ void load_stage(int st, int kcc, int mt, int nt,
                                           uint32_t smbase, int tid)
{
    const int k0 = kcc * BK;
    const __half* As = g_A + (size_t)mt * BM * NF + k0;
    const __half* Bs = g_B + (size_t)k0 * NH + nt * BN;
    const uint32_t sa = smbase + st * ST_BYTES;
    const uint32_t sb = sa + A_ST_BYTES;
#pragma unroll
    for (int h = 0; h < 2; ++h) {
        int id = tid + h * 256;
        int m  = id >> 2;
        int ca = id & 3;
        cpa16(sa + (uint32_t)m * (A_PITCH * 2) + ca * 16,
              As + (size_t)m * NF + ca * 8);
    }
#pragma unroll
    for (int h = 0; h < 4; ++h) {
        int id = tid + h * 256;
        int k  = id >> 5;
        int cb = id & 31;
        cpa16(sb + ((uint32_t)k * 32 + (uint32_t)(cb ^ (k & 7))) * 16,
              Bs + (size_t)k * NH + cb * 8);
    }
}

__global__ __launch_bounds__(256, 1)
void gemm_hmma(const float* __restrict__ b1, const float* __restrict__ W2)
{
    const int tid    = threadIdx.x;
    const int lane   = tid & 31;
    const int wid    = tid >> 5;
    const int warp_m = wid & 1;
    const int warp_n = wid >> 1;
    const int nt     = blockIdx.x;
    const int mt     = blockIdx.y;
    const uint32_t smbase = smem_u32(dynsmem);

    float c[4][8][4];
#pragma unroll
    for (int i = 0; i < 4; ++i)
#pragma unroll
        for (int j = 0; j < 8; ++j)
#pragma unroll
            for (int r = 0; r < 4; ++r) c[i][j][r] = 0.f;

#pragma unroll
    for (int s = 0; s < STAGES - 1; ++s) {
        load_stage(s, s, mt, nt, smbase, tid);
        cp_commit();
    }

    for (int kcc = 0; kcc < KCHUNKS; ++kcc) {
        cp_wait2();
        __syncthreads();

        const int next = kcc + STAGES - 1;
        if (next < KCHUNKS) load_stage(next & (STAGES - 1), next, mt, nt, smbase, tid);
        cp_commit();

        const int st = kcc & (STAGES - 1);
        const uint32_t sa = smbase + st * ST_BYTES;
        const uint32_t sb = sa + A_ST_BYTES;

#pragma unroll
        for (int ks = 0; ks < 2; ++ks) {
            const int k0 = ks * 16;
            uint32_t a[4][4];
#pragma unroll
            for (int i = 0; i < 4; ++i) {
                int m    = warp_m * 64 + i * 16 + (lane & 15);
                int koff = k0 + ((lane >> 4) << 3);
                ldm_x4(a[i], sa + (uint32_t)m * (A_PITCH * 2) + (uint32_t)koff * 2);
            }
            uint32_t b[8][2];
#pragma unroll
            for (int j2 = 0; j2 < 4; ++j2) {
                int k    = k0 + (lane & 15);
                int clog = ((warp_n * 64 + j2 * 16) >> 3) + (lane >> 4);
                uint32_t addr = sb + ((uint32_t)k * 32 + (uint32_t)(clog ^ (k & 7))) * 16;
                uint32_t r0, r1, r2, r3;
                ldm_x4_t(r0, r1, r2, r3, addr);
                b[j2 * 2][0]     = r0; b[j2 * 2][1]     = r1;
                b[j2 * 2 + 1][0] = r2; b[j2 * 2 + 1][1] = r3;
            }
#pragma unroll
            for (int i = 0; i < 4; ++i)
#pragma unroll
                for (int j = 0; j < 8; ++j)
                    mma_fp16(c[i][j], a[i], b[j]);
        }
    }

    __syncthreads();
    float* red = (float*)dynsmem;

    float b1v[8][2], w2a[8][2], w2b[8][2];
#pragma unroll
    for (int j = 0; j < 8; ++j)
#pragma unroll
        for (int cc = 0; cc < 2; ++cc) {
            int gn = nt * BN + warp_n * 64 + j * 8 + (lane & 3) * 2 + cc;
            b1v[j][cc] = b1[gn];
            w2a[j][cc] = W2[gn * 2 + 0];
            w2b[j][cc] = W2[gn * 2 + 1];
        }

#pragma unroll
    for (int i = 0; i < 4; ++i) {
#pragma unroll
        for (int rh = 0; rh < 2; ++rh) {
            float p0 = 0.f, p1 = 0.f;
#pragma unroll
            for (int j = 0; j < 8; ++j)
#pragma unroll
                for (int cc = 0; cc < 2; ++cc) {
                    float h = tanhf(c[i][j][rh * 2 + cc] + b1v[j][cc]);
                    p0 = fmaf(h, w2a[j][cc], p0);
                    p1 = fmaf(h, w2b[j][cc], p1);
                }
            int row  = warp_m * 64 + i * 16 + (lane >> 2) + rh * 8;
            int slot = warp_n * 4 + (lane & 3);
            red[(row * 2 + 0) * 16 + slot] = p0;
            red[(row * 2 + 1) * 16 + slot] = p1;
        }
    }
    __syncthreads();
    {
        int row = tid >> 1, out = tid & 1;
        float s = 0.f;
#pragma unroll
        for (int sl = 0; sl < 16; ++sl) s += red[(row * 2 + out) * 16 + sl];
        g_po[((size_t)(mt * BM + row)) * 4 + nt * 2 + out] = s;
    }
}

// ---------------------------------------------------------------------------
// HMM scan v3: one thread per (batch, chain) pair, driven by visit lists.
// ---------------------------------------------------------------------------
__device__ __forceinline__ float lse2(float a, float b)
{
    float m = fmaxf(a, b);
    float d = fabsf(a - b);
    return m + log1pf(expf(-d));
}

__global__ __launch_bounds__(128)
void scan_kernel(const float* __restrict__ trans_logits,
                 const float* __restrict__ obs_logits,
                 const float* __restrict__ init_logits,
                 const float* __restrict__ b2,
                 float* __restrict__ out)
{
    const int b = blockIdx.x;                       // 0..63
    const int c = blockIdx.y * 128 + threadIdx.x;   // 0..511
    if (c >= NK) return;

    const int vbase = g_vstart[b * (NKP + 1) + c];
    const int vend  = g_vstart[b * (NKP + 1) + c + 1];
    const int n     = vend - vbase;
    if (n == 0) return;

    float t00 = trans_logits[c * 4 + 0];
    float t01 = trans_logits[c * 4 + 1];
    float t10 = trans_logits[c * 4 + 2];
    float t11 = trans_logits[c * 4 + 3];
    float ls0 = lse2(t00, t10);
    float ls1 = lse2(t01, t11);
    float lt00 = t00 - ls0, lt10 = t10 - ls0;
    float lt01 = t01 - ls1, lt11 = t11 - ls1;

    float i0 = init_logits[c * 2 + 0];
    float i1 = init_logits[c * 2 + 1];
    float li = lse2(i0, i1);
    float la0 = i0 - li, la1 = i1 - li;

    float ol00 = obs_logits[c * 4 + 0];
    float ol01 = obs_logits[c * 4 + 1];
    float ol10 = obs_logits[c * 4 + 2];
    float ol11 = obs_logits[c * 4 + 3];

    const float bb0 = b2[0], bb1 = b2[1];
    const uint32_t* vis = &g_visits[b * TLEN + vbase];

    uint32_t last = 0;   // entries are (t<<1)|y; strictly increasing t over processing
    for (int i = 0; i < n; ++i) {
        // select min entry with t > processed-so-far (entries unsorted)
        uint32_t best = 0xFFFFFFFFu;
        for (int j = 0; j < n; ++j) {
            uint32_t e = vis[j];
            if ((i == 0 || e > last) && e < best) best = e;
        }
        last = best;

        const int t = (int)(best >> 1);
        const int y = (int)(best & 1u);
        const size_t m = (size_t)(b * TLEN + t);
        float4 po = *(const float4*)&g_po[m * 4];
        float o0 = bb0 + po.x + po.z;
        float o1 = bb1 + po.y + po.w;

        float e00 = ol00 + o0, e01 = ol01 - o0;
        float l0  = lse2(e00, e01);
        float lo00 = e00 - l0, lo01 = e01 - l0;
        float e10 = ol10 + o1, e11 = ol11 - o1;
        float l1  = lse2(e10, e11);
        float lo10 = e10 - l1, lo11 = e11 - l1;

        float py0 = lse2(lo00 + la0, lo10 + la1);
        float py1 = lse2(lo01 + la0, lo11 + la1);
        float pn  = lse2(py0, py1);
        out[m * 2 + 0] = py0 - pn;
        out[m * 2 + 1] = py1 - pn;

        float lp0 = y ? lo01 : lo00;
        float lp1 = y ? lo11 : lo10;
        float na0 = lse2(lp0 + la0 + lt00, lp1 + la1 + lt01);
        float na1 = lse2(lp0 + la0 + lt10, lp1 + la1 + lt11);
        la0 = na0; la1 = na1;
    }
}

// ---------------------------------------------------------------------------
// Launch
// ---------------------------------------------------------------------------
extern "C" void kernel_launch(void* const* d_in, const int* in_sizes, int n_in,
                              void* d_out, int out_size)
{
    const int*   corr = (const int*)  d_in[0];
    const int*   kc   = (const int*)  d_in[1];
    const float* FM   = (const float*)d_in[2];
    const float* W1   = (const float*)d_in[3];
    const float* b1   = (const float*)d_in[4];
    const float* W2   = (const float*)d_in[5];
    const float* b2   = (const float*)d_in[6];
    const float* trl  = (const float*)d_in[7];
    const float* obl  = (const float*)d_in[8];
    const float* inl  = (const float*)d_in[9];
    float* out = (float*)d_out;

    static bool attr_set = false;
    if (!attr_set) {
        cudaFuncSetAttribute(gemm_hmma,
                             cudaFuncAttributeMaxDynamicSharedMemorySize, DYN_SMEM);
        attr_set = true;
    }

    prep_a_kernel<<<(MROWS * NF) / (256 * 4), 256>>>(FM);
    prep_b_kernel<<<(NF * NH) / (256 * 4), 256>>>(W1);
    build_visits_kernel<<<BATCH, 512>>>(corr, kc);

    gemm_hmma<<<dim3(2, MROWS / BM), 256, DYN_SMEM>>>(b1, W2);

    scan_kernel<<<dim3(BATCH, 4), 128>>>(trl, obl, inl, b2, out);
}